// round 11
// baseline (speedup 1.0000x reference)
#include <cuda_runtime.h>

// Problem constants
#define NB    2
#define NT    5
#define NGRID 1024            // 32*32 spatial points
#define NQ    5120            // NT * NGRID

__device__ __forceinline__ unsigned long long pack2(float a, float b) {
    return ((unsigned long long)__float_as_uint(b) << 32) | __float_as_uint(a);
}

__device__ __forceinline__ void st256(float* p, const unsigned long long u[4]) {
    asm volatile("st.global.v4.b64 [%0], {%1,%2,%3,%4};"
                 :: "l"(p), "l"(u[0]), "l"(u[1]), "l"(u[2]), "l"(u[3]) : "memory");
}

__device__ __forceinline__ float sp10(float x) {
    float z = 10.f * x;
    return (fmaxf(z, 0.f) + log1pf(expf(-fabsf(z)))) * 0.1f;
}

// Decode the 9 stencil coefficients of operator (b, i) at point p.
__device__ __forceinline__ void decode_point(const float* __restrict__ params,
                                             int b, int i, int p, float co[9]) {
    int t = i + 1;
    // kappa / m use the "raw reshape" mixing: flat = p*5 + t over a (5,32,32) block
    int flat = p * 5 + t;
    int tor  = flat >> 10;
    int rem  = flat & 1023;

    const float* Pb = params + b * 35 * NGRID;
    float kap = sp10(Pb[(0  + tor) * NGRID + rem]);
    float m1  =      Pb[(5  + tor) * NGRID + rem];
    float m2  =      Pb[(10 + tor) * NGRID + rem];

    float gam = sp10(Pb[(15 + t) * NGRID + p]);
    float vx  =      Pb[(20 + t) * NGRID + p];
    float vy  =      Pb[(25 + t) * NGRID + p];

    float H11 = gam + vx * vx;
    float H22 = gam + vy * vy;
    float H12 = vx * vy;

    int y = p >> 5, x = p & 31;

    co[4] = kap * kap + 2.f * H11 + 2.f * H22;
    co[5] = (x + 1 < 32)            ? (-H11 + 0.5f * m1) : 0.f;
    co[3] = (x - 1 >= 0)            ? (-H11 - 0.5f * m1) : 0.f;
    co[7] = (y + 1 < 32)            ? (-H22 + 0.5f * m2) : 0.f;
    co[1] = (y - 1 >= 0)            ? (-H22 - 0.5f * m2) : 0.f;
    co[8] = (x + 1 < 32 && y + 1 < 32) ? (-0.5f * H12) : 0.f;
    co[0] = (x - 1 >= 0 && y - 1 >= 0) ? (-0.5f * H12) : 0.f;
    co[2] = (x + 1 < 32 && y - 1 >= 0) ? ( 0.5f * H12) : 0.f;
    co[6] = (x - 1 >= 0 && y + 1 < 32) ? ( 0.5f * H12) : 0.f;
}

// ---------------------------------------------------------------------------
// Single fused kernel, 2 consecutive global rows per block (5120 blocks),
// 8 blocks/SM.
//  Phase 1: 60 threads decode 2 x 30 window points -> sco
//  Phase 2: 50 diag + 18 off-lo + 18 off-hi band values -> smem
//  Phase 3: 2 row-groups x 128 threads; each thread owns 8 columns of one
//           row and issues 5 plain 256-bit stores.
// ---------------------------------------------------------------------------
__global__ void __launch_bounds__(256, 8) q_kernel(const float* __restrict__ params,
                                                   float* __restrict__ out) {
    __shared__ float sco[2][9][32];    // [slot][offset o][local 5x6 point]
    __shared__ float sdiag[2][28];
    __shared__ float slo[2][12];
    __shared__ float shi[2][12];

    int row0 = blockIdx.x << 1;           // 0..10238, step 2
    int b    = row0 >= NQ;
    int R0   = row0 - (b ? NQ : 0);
    int ti   = R0 >> 10;
    int r0   = R0 & 1023;
    int ry   = r0 >> 5;                   // same for both rows (2 | 32)
    int rxb  = r0 & 31;                   // rx of row g is rxb + g
    int tid  = threadIdx.x;

    int iA = (ti == 0) ? 0 : ti - 1;      // diag + off-lo operator
    int iB = (ti < 4) ? ti : 3;           // off-hi operator

    // Phase 1: decode 2 x 30 window points.
    if (tid < 60) {
        int slot = tid >= 30;
        int l    = slot ? tid - 30 : tid;     // local 5x6 index
        int ly = l / 6, lx = l - ly * 6;
        int y = ry - 2 + ly, x = rxb - 2 + lx;
        float co[9] = {0.f, 0.f, 0.f, 0.f, 0.f, 0.f, 0.f, 0.f, 0.f};
        if (y >= 0 && y < 32 && x >= 0 && x < 32)
            decode_point(params, b, slot ? iB : iA, (y << 5) + x, co);
#pragma unroll
        for (int o = 0; o < 9; ++o)
            sco[slot][o][l] = co[o];
    }
    __syncthreads();

    // Phase 2: band values for the 2 rows.
    if (tid < 50) {
        int g   = tid >= 25;
        int o25 = g ? tid - 25 : tid;
        int rx  = rxb + g;
        int r   = (ry << 5) + rx;
        int dy = o25 / 5 - 2, dx = o25 % 5 - 2;
        int cy = ry + dy, cx = rx + dx;
        int lr = 14 + g;                        // r's local index: 2*6 + (g+2)
        float val = 0.f;
        if (cy >= 0 && cy < 32 && cx >= 0 && cx < 32) {
            int lc = (dy + 2) * 6 + (g + dx + 2);
            if (ti == 0) {
                float acc = 0.f;
#pragma unroll
                for (int dky = -1; dky <= 1; ++dky)
#pragma unroll
                for (int dkx = -1; dkx <= 1; ++dkx) {
                    int ky = ry + dky, kx = rx + dkx;
                    int ody = cy - ky, odx = cx - kx;
                    if (ky >= 0 && ky < 32 && kx >= 0 && kx < 32 &&
                        ody >= -1 && ody <= 1 && odx >= -1 && odx <= 1) {
                        int lk = (dky + 2) * 6 + (g + dkx + 2);
                        float a  = sco[0][(1 - dky) * 3 + (1 - dkx)][lk];
                        float bb = sco[0][(ody + 1) * 3 + (odx + 1)][lk];
                        acc = fmaf(a, bb, acc);
                    }
                }
                val = acc + ((o25 == 12) ? 1.05f : 0.f);
            } else {
                int c = (cy << 5) + cx;
                float acc1 = 0.f, acc2 = 0.f;
#pragma unroll
                for (int dky = -1; dky <= 1; ++dky)
#pragma unroll
                for (int dkx = -1; dkx <= 1; ++dkx) {
                    int ky = ry + dky, kx = rx + dkx;
                    int ody = cy - ky, odx = cx - kx;
                    if (ky >= 0 && ky < 32 && kx >= 0 && kx < 32 &&
                        ody >= -1 && ody <= 1 && odx >= -1 && odx <= 1) {
                        int k  = (ky << 5) + kx;
                        int lk = (dky + 2) * 6 + (g + dkx + 2);
                        float dkr = (k == r) ? 1.f : 0.f;
                        float dkc = (k == c) ? 1.f : 0.f;
                        float iM_rk = sco[0][(dky + 1) * 3 + (dkx + 1)][lr] + dkr;
                        float iM_kr = sco[0][(1 - dky) * 3 + (1 - dkx)][lk] + dkr;
                        float iM_kc = sco[0][(ody + 1) * 3 + (odx + 1)][lk] + dkc;
                        float iM_ck = sco[0][(1 - ody) * 3 + (1 - odx)][lc] + dkc;
                        acc1 = fmaf(iM_rk, iM_kc, acc1);
                        acc2 = fmaf(iM_ck, iM_kr, acc2);
                    }
                }
                val = 0.5f * (acc1 + acc2);
                if (o25 == 12) val += (ti == 4) ? 0.05f : 1.05f;
            }
        }
        sdiag[g][o25] = val;
    } else if (tid >= 64 && tid < 82) {
        // off-lo: -0.5*(A_{ti-1}[r][c] + A_{ti-1}[c][r] + 2*delta), slot 0
        int t2 = tid - 64;
        int g  = t2 >= 9;
        int o9 = g ? t2 - 9 : t2;
        int rx = rxb + g;
        int dy = o9 / 3 - 1, dx = o9 % 3 - 1;
        int cy = ry + dy, cx = rx + dx;
        float val = 0.f;
        if (cy >= 0 && cy < 32 && cx >= 0 && cx < 32) {
            int lc = (dy + 2) * 6 + (g + dx + 2);
            float a  = sco[0][o9][14 + g];
            float bb = sco[0][8 - o9][lc];
            val = -0.5f * (a + bb + ((o9 == 4) ? 2.f : 0.f));
        }
        slo[g][o9] = val;
    } else if (tid >= 96 && tid < 114) {
        // off-hi: operator ti, slot 1
        int t2 = tid - 96;
        int g  = t2 >= 9;
        int o9 = g ? t2 - 9 : t2;
        int rx = rxb + g;
        int dy = o9 / 3 - 1, dx = o9 % 3 - 1;
        int cy = ry + dy, cx = rx + dx;
        float val = 0.f;
        if (cy >= 0 && cy < 32 && cx >= 0 && cx < 32) {
            int lc = (dy + 2) * 6 + (g + dx + 2);
            float a  = sco[1][o9][14 + g];
            float bb = sco[1][8 - o9][lc];
            val = -0.5f * (a + bb + ((o9 == 4) ? 2.f : 0.f));
        }
        shi[g][o9] = val;
    }
    __syncthreads();

    // Phase 3: 2 row-groups x 128 threads; each thread owns 8 columns.
    int g   = tid >> 7;                   // row group 0/1
    int lid = tid & 127;
    int c0  = lid << 3;                   // first of 8 columns (8 | 32 -> one y-row)
    int dy  = (c0 >> 5) - ry;
    int rx  = rxb + g;
    bool in2y = (dy >= -2 && dy <= 2);
    bool in1y = (dy >= -1 && dy <= 1);
    bool has_lo = (ti > 0), has_hi = (ti < 4);

    unsigned long long zu[4] = {0ull, 0ull, 0ull, 0ull};
    unsigned long long du[4] = {0ull, 0ull, 0ull, 0ull};
    unsigned long long lou[4] = {0ull, 0ull, 0ull, 0ull};
    unsigned long long hiu[4] = {0ull, 0ull, 0ull, 0ull};

    if (in2y) {
        int dxb = (c0 & 31) - rx;
        const float* drow = &sdiag[g][(dy + 2) * 5 + 2];
        float vd[8];
#pragma unroll
        for (int j = 0; j < 8; ++j) {
            int dx = dxb + j;
            vd[j] = (dx >= -2 && dx <= 2) ? drow[dx] : 0.f;
        }
#pragma unroll
        for (int j = 0; j < 4; ++j) du[j] = pack2(vd[2*j], vd[2*j+1]);

        if (in1y) {
            const float* lorow = &slo[g][(dy + 1) * 3 + 1];
            const float* hirow = &shi[g][(dy + 1) * 3 + 1];
            float vl[8], vh[8];
#pragma unroll
            for (int j = 0; j < 8; ++j) {
                int dx = dxb + j;
                bool in1 = (dx >= -1 && dx <= 1);
                vl[j] = (in1 && has_lo) ? lorow[dx] : 0.f;
                vh[j] = (in1 && has_hi) ? hirow[dx] : 0.f;
            }
#pragma unroll
            for (int j = 0; j < 4; ++j) {
                lou[j] = pack2(vl[2*j], vl[2*j+1]);
                hiu[j] = pack2(vh[2*j], vh[2*j+1]);
            }
        }
    }

    float* base = out + (long)(row0 + g) * 5120 + c0;
#pragma unroll
    for (int tj = 0; tj < 5; ++tj) {
        const unsigned long long* u = zu;
        if (tj == ti)          u = du;
        else if (tj == ti - 1) u = lou;
        else if (tj == ti + 1) u = hiu;
        st256(base + tj * 1024, u);
    }
}

extern "C" void kernel_launch(void* const* d_in, const int* in_sizes, int n_in,
                              void* d_out, int out_size) {
    const float* params = (const float*)d_in[0];
    float* out = (float*)d_out;

    q_kernel<<<(NB * NQ) / 2, 256>>>(params, out);
}

// round 12
// speedup vs baseline: 1.6004x; 1.6004x over previous
#include <cuda_runtime.h>

// Problem constants
#define NB    2
#define NT    5
#define NGRID 1024            // 32*32 spatial points
#define NQ    5120            // NT * NGRID

__device__ __forceinline__ float sp10(float x) {
    float z = 10.f * x;
    return (fmaxf(z, 0.f) + log1pf(expf(-fabsf(z)))) * 0.1f;
}

// Decode the 9 stencil coefficients of operator (b, i) at point p.
__device__ __forceinline__ void decode_point(const float* __restrict__ params,
                                             int b, int i, int p, float co[9]) {
    int t = i + 1;
    // kappa / m use the "raw reshape" mixing: flat = p*5 + t over a (5,32,32) block
    int flat = p * 5 + t;
    int tor  = flat >> 10;
    int rem  = flat & 1023;

    const float* Pb = params + b * 35 * NGRID;
    float kap = sp10(Pb[(0  + tor) * NGRID + rem]);
    float m1  =      Pb[(5  + tor) * NGRID + rem];
    float m2  =      Pb[(10 + tor) * NGRID + rem];

    float gam = sp10(Pb[(15 + t) * NGRID + p]);
    float vx  =      Pb[(20 + t) * NGRID + p];
    float vy  =      Pb[(25 + t) * NGRID + p];

    float H11 = gam + vx * vx;
    float H22 = gam + vy * vy;
    float H12 = vx * vy;

    int y = p >> 5, x = p & 31;

    co[4] = kap * kap + 2.f * H11 + 2.f * H22;
    co[5] = (x + 1 < 32)            ? (-H11 + 0.5f * m1) : 0.f;
    co[3] = (x - 1 >= 0)            ? (-H11 - 0.5f * m1) : 0.f;
    co[7] = (y + 1 < 32)            ? (-H22 + 0.5f * m2) : 0.f;
    co[1] = (y - 1 >= 0)            ? (-H22 - 0.5f * m2) : 0.f;
    co[8] = (x + 1 < 32 && y + 1 < 32) ? (-0.5f * H12) : 0.f;
    co[0] = (x - 1 >= 0 && y - 1 >= 0) ? (-0.5f * H12) : 0.f;
    co[2] = (x + 1 < 32 && y - 1 >= 0) ? ( 0.5f * H12) : 0.f;
    co[6] = (x - 1 >= 0 && y + 1 < 32) ? ( 0.5f * H12) : 0.f;
}

// ---------------------------------------------------------------------------
// Single fused kernel: 512 threads, 4 consecutive global rows per block
// (2560 blocks), 4 blocks/SM -> 64 resident warps.
// Rows r0..r0+3 share (b, ti, ry); decode window y in [ry-2,ry+2],
// x in [rxb-2, rxb+5]: 5x8 = 40 points per operator, 2 operators.
//  Phase 1: 80 threads decode -> sco[2][9][40]
//  Phase 2: 100 threads diag (4 rows x 25), 36 off-lo, 36 off-hi -> smem
//  Phase 3: 4 row-groups x 128 threads; each thread owns two 4-column quads
//           of one row -> 10 fully-coalesced float4 stores.
// ---------------------------------------------------------------------------
__global__ void __launch_bounds__(512, 4) q_kernel(const float* __restrict__ params,
                                                   float4* __restrict__ out) {
    __shared__ float sco[2][9][40];    // [slot][offset o][local 5x8 point]
    __shared__ float sdiag[4][28];
    __shared__ float slo[4][12];
    __shared__ float shi[4][12];

    int row0 = blockIdx.x << 2;           // 0..10236, step 4
    int b    = row0 >= NQ;
    int R0   = row0 - (b ? NQ : 0);
    int ti   = R0 >> 10;
    int r0   = R0 & 1023;
    int ry   = r0 >> 5;                   // same for all 4 rows (4 | 32)
    int rxb  = r0 & 31;                   // rx of row g is rxb + g
    int tid  = threadIdx.x;

    int iA = (ti == 0) ? 0 : ti - 1;      // diag + off-lo operator
    int iB = (ti < 4) ? ti : 3;           // off-hi operator

    // Phase 1: decode 2 x 40 window points.
    if (tid < 80) {
        int slot = tid >= 40;
        int l    = slot ? tid - 40 : tid;     // local 5x8 index
        int ly = l >> 3, lx = l & 7;
        int y = ry - 2 + ly, x = rxb - 2 + lx;
        float co[9] = {0.f, 0.f, 0.f, 0.f, 0.f, 0.f, 0.f, 0.f, 0.f};
        if (y >= 0 && y < 32 && x >= 0 && x < 32)
            decode_point(params, b, slot ? iB : iA, (y << 5) + x, co);
#pragma unroll
        for (int o = 0; o < 9; ++o)
            sco[slot][o][l] = co[o];
    }
    __syncthreads();

    // Phase 2: band values for the 4 rows.
    if (tid < 100) {
        int g   = tid / 25;
        int o25 = tid - g * 25;
        int rx  = rxb + g;
        int r   = (ry << 5) + rx;
        int dy = o25 / 5 - 2, dx = o25 % 5 - 2;
        int cy = ry + dy, cx = rx + dx;
        int lr = 18 + g;                        // r's local index: 2*8 + (g+2)
        float val = 0.f;
        if (cy >= 0 && cy < 32 && cx >= 0 && cx < 32) {
            int lc = (dy + 2) * 8 + (g + dx + 2);
            if (ti == 0) {
                float acc = 0.f;
#pragma unroll
                for (int dky = -1; dky <= 1; ++dky)
#pragma unroll
                for (int dkx = -1; dkx <= 1; ++dkx) {
                    int ky = ry + dky, kx = rx + dkx;
                    int ody = cy - ky, odx = cx - kx;
                    if (ky >= 0 && ky < 32 && kx >= 0 && kx < 32 &&
                        ody >= -1 && ody <= 1 && odx >= -1 && odx <= 1) {
                        int lk = (dky + 2) * 8 + (g + dkx + 2);
                        float a  = sco[0][(1 - dky) * 3 + (1 - dkx)][lk];
                        float bb = sco[0][(ody + 1) * 3 + (odx + 1)][lk];
                        acc = fmaf(a, bb, acc);
                    }
                }
                val = acc + ((o25 == 12) ? 1.05f : 0.f);
            } else {
                int c = (cy << 5) + cx;
                float acc1 = 0.f, acc2 = 0.f;
#pragma unroll
                for (int dky = -1; dky <= 1; ++dky)
#pragma unroll
                for (int dkx = -1; dkx <= 1; ++dkx) {
                    int ky = ry + dky, kx = rx + dkx;
                    int ody = cy - ky, odx = cx - kx;
                    if (ky >= 0 && ky < 32 && kx >= 0 && kx < 32 &&
                        ody >= -1 && ody <= 1 && odx >= -1 && odx <= 1) {
                        int k  = (ky << 5) + kx;
                        int lk = (dky + 2) * 8 + (g + dkx + 2);
                        float dkr = (k == r) ? 1.f : 0.f;
                        float dkc = (k == c) ? 1.f : 0.f;
                        float iM_rk = sco[0][(dky + 1) * 3 + (dkx + 1)][lr] + dkr;
                        float iM_kr = sco[0][(1 - dky) * 3 + (1 - dkx)][lk] + dkr;
                        float iM_kc = sco[0][(ody + 1) * 3 + (odx + 1)][lk] + dkc;
                        float iM_ck = sco[0][(1 - ody) * 3 + (1 - odx)][lc] + dkc;
                        acc1 = fmaf(iM_rk, iM_kc, acc1);
                        acc2 = fmaf(iM_ck, iM_kr, acc2);
                    }
                }
                val = 0.5f * (acc1 + acc2);
                if (o25 == 12) val += (ti == 4) ? 0.05f : 1.05f;
            }
        }
        sdiag[g][o25] = val;
    } else if (tid >= 128 && tid < 164) {
        // off-lo: -0.5*(A_{ti-1}[r][c] + A_{ti-1}[c][r] + 2*delta), slot 0
        int t2 = tid - 128;
        int g  = t2 / 9;
        int o9 = t2 - g * 9;
        int rx = rxb + g;
        int dy = o9 / 3 - 1, dx = o9 % 3 - 1;
        int cy = ry + dy, cx = rx + dx;
        float val = 0.f;
        if (cy >= 0 && cy < 32 && cx >= 0 && cx < 32) {
            int lc = (dy + 2) * 8 + (g + dx + 2);
            float a  = sco[0][o9][18 + g];
            float bb = sco[0][8 - o9][lc];
            val = -0.5f * (a + bb + ((o9 == 4) ? 2.f : 0.f));
        }
        slo[g][o9] = val;
    } else if (tid >= 192 && tid < 228) {
        // off-hi: operator ti, slot 1
        int t2 = tid - 192;
        int g  = t2 / 9;
        int o9 = t2 - g * 9;
        int rx = rxb + g;
        int dy = o9 / 3 - 1, dx = o9 % 3 - 1;
        int cy = ry + dy, cx = rx + dx;
        float val = 0.f;
        if (cy >= 0 && cy < 32 && cx >= 0 && cx < 32) {
            int lc = (dy + 2) * 8 + (g + dx + 2);
            float a  = sco[1][o9][18 + g];
            float bb = sco[1][8 - o9][lc];
            val = -0.5f * (a + bb + ((o9 == 4) ? 2.f : 0.f));
        }
        shi[g][o9] = val;
    }
    __syncthreads();

    // Phase 3: 4 row-groups x 128 threads; each thread owns two 4-col quads
    // (cols [4*lid, 4*lid+4) and [512+4*lid, 512+4*lid+4)) of one row.
    int g   = tid >> 7;                   // row group 0..3
    int lid = tid & 127;
    int rx  = rxb + g;
    bool has_lo = (ti > 0), has_hi = (ti < 4);
    float4 z = make_float4(0.f, 0.f, 0.f, 0.f);

    float4* base = out + (long)(row0 + g) * 1280 + lid;

#pragma unroll
    for (int h = 0; h < 2; ++h) {
        int c0 = (lid << 2) + (h << 9);   // 4*lid + 512*h
        int dy = (c0 >> 5) - ry;
        float4 d4 = z, lo4 = z, hi4 = z;

        if (dy >= -2 && dy <= 2) {
            int dxb = (c0 & 31) - rx;
            const float* drow = &sdiag[g][(dy + 2) * 5 + 2];
            float vd[4];
#pragma unroll
            for (int j = 0; j < 4; ++j) {
                int dx = dxb + j;
                vd[j] = (dx >= -2 && dx <= 2) ? drow[dx] : 0.f;
            }
            d4 = make_float4(vd[0], vd[1], vd[2], vd[3]);

            if (dy >= -1 && dy <= 1) {
                const float* lorow = &slo[g][(dy + 1) * 3 + 1];
                const float* hirow = &shi[g][(dy + 1) * 3 + 1];
                float vl[4], vh[4];
#pragma unroll
                for (int j = 0; j < 4; ++j) {
                    int dx = dxb + j;
                    bool in1 = (dx >= -1 && dx <= 1);
                    vl[j] = (in1 && has_lo) ? lorow[dx] : 0.f;
                    vh[j] = (in1 && has_hi) ? hirow[dx] : 0.f;
                }
                lo4 = make_float4(vl[0], vl[1], vl[2], vl[3]);
                hi4 = make_float4(vh[0], vh[1], vh[2], vh[3]);
            }
        }

        float4* basep = base + (h << 7);  // +128 float4 for second quad
#pragma unroll
        for (int tj = 0; tj < 5; ++tj) {
            float4 v = z;
            if (tj == ti)          v = d4;
            else if (tj == ti - 1) v = lo4;
            else if (tj == ti + 1) v = hi4;
            basep[tj * 256] = v;
        }
    }
}

extern "C" void kernel_launch(void* const* d_in, const int* in_sizes, int n_in,
                              void* d_out, int out_size) {
    const float* params = (const float*)d_in[0];
    float4* out = (float4*)d_out;

    q_kernel<<<(NB * NQ) / 4, 512>>>(params, out);
}